// round 9
// baseline (speedup 1.0000x reference)
#include <cuda_runtime.h>
#include <cuda_fp16.h>
#include <cstdint>

// ---------------------------------------------------------------------------
// Problem shape (fixed by dataset)
// ---------------------------------------------------------------------------
static constexpr int GM = 8192;          // batch
static constexpr int GN = 512;           // out_count
static constexpr int GIN = 512;          // in_count
static constexpr int NB = 8;             // num_basis
static constexpr int GK = GIN * NB;      // 4096 (reduction dim, (i,m) order)

// GEMM tiling: BM=128, BN=256, BK=64; 8 warps in 2(M) x 4(N); warp tile 64x64
static constexpr int BM = 128, BN = 256, BK = 64;
static constexpr int BSTAGES = 3;        // B pipeline stages
static constexpr int KT = GK / BK;       // 64 k-tiles
static constexpr int LDS = BK + 8;       // 72 halves row stride (144B, conflict-free)
static constexpr int A_STAGE_BYTES = BM * LDS * 2;   // 18432 (A double-buffered)
static constexpr int B_STAGE_BYTES = BN * LDS * 2;   // 36864

// smem layout (bytes)
static constexpr int FG_F_OFF = 0;                   // 16384 (512*8 fp32)
static constexpr int FG_G_OFF = 16384;               // 16384
static constexpr int A_OFF    = 32768;               // 2 * 18432 = 36864
static constexpr int B_OFF    = A_OFF + 2 * A_STAGE_BYTES;   // 69632
static constexpr int SMEM_BYTES = B_OFF + BSTAGES * B_STAGE_BYTES; // 180224

// Scratch (allowed: __device__ globals)
__device__ __half g_coefh[(size_t)GN * GK];   // 4 MB, [j][i*8+m]

// ---------------------------------------------------------------------------
// Helpers
// ---------------------------------------------------------------------------
__device__ __forceinline__ uint32_t h2_as_u32(__half2 v) {
    union { __half2 h; uint32_t u; } cvt;
    cvt.h = v;
    return cvt.u;
}

__device__ __forceinline__ uint32_t smem_u32(const void* p) {
    uint32_t a;
    asm("{ .reg .u64 t; cvta.to.shared.u64 t, %1; cvt.u32.u64 %0, t; }"
        : "=r"(a) : "l"(p));
    return a;
}

__device__ __forceinline__ void cp16(uint32_t dst, const void* src) {
    asm volatile("cp.async.cg.shared.global [%0], [%1], 16;\n" :: "r"(dst), "l"(src));
}

__device__ __forceinline__ void ldmatrix_x4(uint32_t* r, uint32_t addr) {
    asm volatile("ldmatrix.sync.aligned.m8n8.x4.shared.b16 {%0,%1,%2,%3}, [%4];"
                 : "=r"(r[0]), "=r"(r[1]), "=r"(r[2]), "=r"(r[3]) : "r"(addr));
}

__device__ __forceinline__ void mma_16816(float* d, const uint32_t* a, const uint32_t* b) {
    asm volatile(
        "mma.sync.aligned.m16n8k16.row.col.f32.f16.f16.f32 "
        "{%0,%1,%2,%3}, {%4,%5,%6,%7}, {%8,%9}, {%0,%1,%2,%3};"
        : "+f"(d[0]), "+f"(d[1]), "+f"(d[2]), "+f"(d[3])
        : "r"(a[0]), "r"(a[1]), "r"(a[2]), "r"(a[3]), "r"(b[0]), "r"(b[1]));
}

// ---------------------------------------------------------------------------
// Pass 1: coeffs fp32 -> fp16 (same [j][i*8+m] layout)
// ---------------------------------------------------------------------------
__global__ void __launch_bounds__(256) coef_convert_kernel(const float* __restrict__ c) {
    int idx = blockIdx.x * blockDim.x + threadIdx.x;   // per 4 elements
    float4 v = reinterpret_cast<const float4*>(c)[idx];
    __half2 a = __floats2half2_rn(v.x, v.y);
    __half2 b = __floats2half2_rn(v.z, v.w);
    uint2 o;
    o.x = h2_as_u32(a);
    o.y = h2_as_u32(b);
    reinterpret_cast<uint2*>(g_coefh)[idx] = o;
}

// ---------------------------------------------------------------------------
// Pass 2: FUSED basis + HMMA GEMM
//   out[M,N] = S[M,K] * coefh[N,K]^T,  S computed on the fly:
//   S[b][i*8+m] = 0.5*tanh(slope[i][m]*(x[b][i]-center[i][m])) + 0.5
// A tile (128x64 fp16) produced in-kernel per k-tile (double-buffered),
// B via 3-stage cp.async, mma.sync m16n8k16, frag double-buffering.
// ---------------------------------------------------------------------------
__global__ void __launch_bounds__(256, 1) gemm_kernel(const float* __restrict__ x,
                                                      const float* __restrict__ centers,
                                                      const float* __restrict__ slopes,
                                                      float* __restrict__ out) {
    extern __shared__ char smbase[];
    const uint32_t sb32 = smem_u32(smbase);

    float* fgF = reinterpret_cast<float*>(smbase + FG_F_OFF);   // [i*8+m] = slope
    float* fgG = reinterpret_cast<float*>(smbase + FG_G_OFF);   // [i*8+m] = -slope*center
    const uint32_t sA0 = sb32 + A_OFF;
    const uint32_t sB0 = sb32 + B_OFF;

    const int tid = threadIdx.x;
    const int wid = tid >> 5;
    const int lid = tid & 31;
    const int wm = wid & 1;        // warp M index (0..1)  -> 64-row slab
    const int wn = wid >> 1;       // warp N index (0..3)  -> 64-col slab
    const int m0 = blockIdx.y * BM;
    const int n0 = blockIdx.x * BN;

    // ---- precompute f,g tables into smem (4096 fp32 each) ----
    {
        const float4* sl4 = reinterpret_cast<const float4*>(slopes);
        const float4* ce4 = reinterpret_cast<const float4*>(centers);
        float4* f4 = reinterpret_cast<float4*>(fgF);
        float4* g4 = reinterpret_cast<float4*>(fgG);
#pragma unroll
        for (int j = 0; j < 4; j++) {
            int c = tid + j * 256;
            float4 s = sl4[c], cc = ce4[c];
            f4[c] = s;
            g4[c] = make_float4(-s.x * cc.x, -s.y * cc.y, -s.z * cc.z, -s.w * cc.w);
        }
    }
    // RACE FIX (R8 bug): fg tables must be visible to ALL threads before the
    // prologue produce_A(0) reads them.
    __syncthreads();

    const __half* Bbase = g_coefh + (size_t)n0 * GK;

    // ---- B loader: 2048 16B chunks per stage, 8 per thread ----
    auto load_B = [&](int kt) {
        int stg = kt % BSTAGES;
        uint32_t sbm = sB0 + stg * B_STAGE_BYTES;
        int kofs = kt * BK;
#pragma unroll
        for (int j = 0; j < 8; j++) {
            int c = tid + j * 256;
            int row = c >> 3;
            int cu = c & 7;
            uint32_t so = (uint32_t)(row * LDS + cu * 8) * 2;
            cp16(sbm + so, Bbase + (size_t)row * GK + kofs + cu * 8);
        }
        asm volatile("cp.async.commit_group;\n" ::: "memory");
    };

    // ---- A producer: thread t handles i_local = t&7, rows rgrp*4..+3 ----
    const int i_local = tid & 7;
    const int rgrp = tid >> 3;           // 0..31 -> rows rgrp*4 .. +3
    const float* xrow0 = x + (size_t)(m0 + rgrp * 4) * GIN;

    auto fetch_x = [&](int kt, float* xr) {
        int i = kt * 8 + i_local;
#pragma unroll
        for (int r = 0; r < 4; r++)
            xr[r] = xrow0[(size_t)r * GIN + i];
    };

    auto produce_A = [&](int kt, const float* xr) {
        uint32_t abuf_off = A_OFF + (kt & 1) * A_STAGE_BYTES;
        uint4* ap = reinterpret_cast<uint4*>(smbase + abuf_off);
        int i = kt * 8 + i_local;
        float f0[8], g0[8];
        const float4* fp4 = reinterpret_cast<const float4*>(fgF + i * 8);
        const float4* gp4 = reinterpret_cast<const float4*>(fgG + i * 8);
        float4 fa = fp4[0], fb = fp4[1];
        float4 ga = gp4[0], gb = gp4[1];
        f0[0] = fa.x; f0[1] = fa.y; f0[2] = fa.z; f0[3] = fa.w;
        f0[4] = fb.x; f0[5] = fb.y; f0[6] = fb.z; f0[7] = fb.w;
        g0[0] = ga.x; g0[1] = ga.y; g0[2] = ga.z; g0[3] = ga.w;
        g0[4] = gb.x; g0[5] = gb.y; g0[6] = gb.z; g0[7] = gb.w;
#pragma unroll
        for (int r = 0; r < 4; r++) {
            __half h[8];
#pragma unroll
            for (int m = 0; m < 8; m++) {
                float t = fmaf(f0[m], xr[r], g0[m]);
                float th;
                asm("tanh.approx.f32 %0, %1;" : "=f"(th) : "f"(t));
                h[m] = __float2half_rn(fmaf(0.5f, th, 0.5f));
            }
            uint4 o;
            o.x = h2_as_u32(__halves2half2(h[0], h[1]));
            o.y = h2_as_u32(__halves2half2(h[2], h[3]));
            o.z = h2_as_u32(__halves2half2(h[4], h[5]));
            o.w = h2_as_u32(__halves2half2(h[6], h[7]));
            int row = rgrp * 4 + r;
            ap[row * 9 + i_local] = o;   // 9 uint4 per 72-half row
        }
    };

    // ---- prologue ----
    {
        float xr0[4];
        fetch_x(0, xr0);
        produce_A(0, xr0);
    }
    load_B(0);
    load_B(1);

    float d[4][8][4];
#pragma unroll
    for (int mi = 0; mi < 4; mi++)
#pragma unroll
        for (int ni = 0; ni < 8; ni++)
#pragma unroll
            for (int q = 0; q < 4; q++) d[mi][ni][q] = 0.0f;

    // ldmatrix lane addressing (halves)
    const int a_row = wm * 64 + (lid & 15);
    const int a_col = (lid >> 4) * 8;
    const int b_row = wn * 64 + (lid & 7) + (lid >> 4) * 8;
    const int b_col = ((lid >> 3) & 1) * 8;

    uint32_t afr[2][4][4];
    uint32_t bfr[2][8][2];

    auto ld_frags = [&](uint32_t sa, uint32_t sbm, int ks, int buf) {
#pragma unroll
        for (int mi = 0; mi < 4; mi++) {
            uint32_t addr = sa + (uint32_t)((a_row + mi * 16) * LDS + ks * 16 + a_col) * 2;
            ldmatrix_x4(afr[buf][mi], addr);
        }
#pragma unroll
        for (int p = 0; p < 4; p++) {
            uint32_t t[4];
            uint32_t addr = sbm + (uint32_t)((b_row + p * 16) * LDS + ks * 16 + b_col) * 2;
            ldmatrix_x4(t, addr);
            bfr[buf][2 * p][0] = t[0]; bfr[buf][2 * p][1] = t[1];
            bfr[buf][2 * p + 1][0] = t[2]; bfr[buf][2 * p + 1][1] = t[3];
        }
    };

    __syncthreads();   // A(0) visible

    for (int kt = 0; kt < KT; kt++) {
        asm volatile("cp.async.wait_group 1;\n" ::: "memory");
        __syncthreads();

        // next B stage
        if (kt + 2 < KT) {
            load_B(kt + 2);
        } else {
            asm volatile("cp.async.commit_group;\n" ::: "memory");
        }

        // prefetch x for A(kt+1): LDG latency hides under the MMA block
        float xn[4];
        if (kt + 1 < KT) fetch_x(kt + 1, xn);

        uint32_t sa = sA0 + (kt & 1) * A_STAGE_BYTES;
        uint32_t sbm = sB0 + (kt % BSTAGES) * B_STAGE_BYTES;

        ld_frags(sa, sbm, 0, 0);
#pragma unroll
        for (int ks = 0; ks < 4; ks++) {
            int cur = ks & 1;
            if (ks < 3) ld_frags(sa, sbm, ks + 1, cur ^ 1);
#pragma unroll
            for (int mi = 0; mi < 4; mi++)
#pragma unroll
                for (int ni = 0; ni < 8; ni++)
                    mma_16816(d[mi][ni], afr[cur][mi], bfr[cur][ni]);
        }

        // produce A for next k-tile into the alternate buffer
        if (kt + 1 < KT) produce_A(kt + 1, xn);
    }

    // Epilogue: direct fp32 stores.
    const int er = m0 + wm * 64 + (lid >> 2);
    const int ec = n0 + wn * 64 + (lid & 3) * 2;
#pragma unroll
    for (int mi = 0; mi < 4; mi++) {
#pragma unroll
        for (int ni = 0; ni < 8; ni++) {
            int r = er + mi * 16;
            int c = ec + ni * 8;
            float2 v0 = make_float2(d[mi][ni][0], d[mi][ni][1]);
            float2 v1 = make_float2(d[mi][ni][2], d[mi][ni][3]);
            *reinterpret_cast<float2*>(out + (size_t)r * GN + c) = v0;
            *reinterpret_cast<float2*>(out + (size_t)(r + 8) * GN + c) = v1;
        }
    }
}

// ---------------------------------------------------------------------------
// Launch
// ---------------------------------------------------------------------------
extern "C" void kernel_launch(void* const* d_in, const int* in_sizes, int n_in,
                              void* d_out, int out_size) {
    const float* x       = (const float*)d_in[0];   // (8192, 512)
    const float* coeffs  = (const float*)d_in[1];   // (512, 512, 8)
    const float* centers = (const float*)d_in[2];   // (512, 8)
    const float* slopes  = (const float*)d_in[3];   // (512, 8)
    float* out = (float*)d_out;                     // (8192, 512)

    // Pass 1: coeffs fp32 -> fp16
    coef_convert_kernel<<<(GN * GK / 4) / 256, 256>>>(coeffs);

    // Pass 2: fused basis + HMMA GEMM
    cudaFuncSetAttribute(gemm_kernel, cudaFuncAttributeMaxDynamicSharedMemorySize,
                         SMEM_BYTES);
    dim3 grid(GN / BN, GM / BM);   // (2, 64)
    gemm_kernel<<<grid, 256, SMEM_BYTES>>>(x, centers, slopes, out);
}

// round 10
// speedup vs baseline: 1.2423x; 1.2423x over previous
#include <cuda_runtime.h>
#include <cuda_fp16.h>
#include <cstdint>

// ---------------------------------------------------------------------------
// Problem shape (fixed by dataset)
// ---------------------------------------------------------------------------
static constexpr int GM = 8192;          // batch
static constexpr int GN = 512;           // out_count
static constexpr int GIN = 512;          // in_count
static constexpr int NB = 8;             // num_basis
static constexpr int GK = GIN * NB;      // 4096 (reduction dim, (i,m) order)

// GEMM tiling: BM=128, BN=256, BK=64; warp-specialized CTA:
//   warps 0-7  : consumers, 2(M) x 4(N), warp tile 64x64, MMA only
//   warps 8-11 : producers, A-tile tanh production + all B cp.async
static constexpr int BM = 128, BN = 256, BK = 64;
static constexpr int BSTAGES = 3;        // B pipeline stages
static constexpr int KT = GK / BK;       // 64 k-tiles
static constexpr int LDS = BK + 8;       // 72 halves row stride (144B, conflict-free)
static constexpr int A_STAGE_BYTES = BM * LDS * 2;   // 18432 (A double-buffered)
static constexpr int B_STAGE_BYTES = BN * LDS * 2;   // 36864

static constexpr int A_OFF = 0;                              // 2 * 18432
static constexpr int B_OFF = 2 * A_STAGE_BYTES;              // 36864
static constexpr int SMEM_BYTES = B_OFF + BSTAGES * B_STAGE_BYTES;  // 147456

static constexpr int THREADS = 384;      // 256 consumers + 128 producers

// Scratch (allowed: __device__ globals)
__device__ __half g_coefh[(size_t)GN * GK];   // 4 MB, [j][i*8+m]

// ---------------------------------------------------------------------------
// Helpers
// ---------------------------------------------------------------------------
__device__ __forceinline__ uint32_t h2_as_u32(__half2 v) {
    union { __half2 h; uint32_t u; } cvt;
    cvt.h = v;
    return cvt.u;
}

__device__ __forceinline__ uint32_t smem_u32(const void* p) {
    uint32_t a;
    asm("{ .reg .u64 t; cvta.to.shared.u64 t, %1; cvt.u32.u64 %0, t; }"
        : "=r"(a) : "l"(p));
    return a;
}

__device__ __forceinline__ void cp16(uint32_t dst, const void* src) {
    asm volatile("cp.async.cg.shared.global [%0], [%1], 16;\n" :: "r"(dst), "l"(src));
}

__device__ __forceinline__ void ldmatrix_x4(uint32_t* r, uint32_t addr) {
    asm volatile("ldmatrix.sync.aligned.m8n8.x4.shared.b16 {%0,%1,%2,%3}, [%4];"
                 : "=r"(r[0]), "=r"(r[1]), "=r"(r[2]), "=r"(r[3]) : "r"(addr));
}

__device__ __forceinline__ void mma_16816(float* d, const uint32_t* a, const uint32_t* b) {
    asm volatile(
        "mma.sync.aligned.m16n8k16.row.col.f32.f16.f16.f32 "
        "{%0,%1,%2,%3}, {%4,%5,%6,%7}, {%8,%9}, {%0,%1,%2,%3};"
        : "+f"(d[0]), "+f"(d[1]), "+f"(d[2]), "+f"(d[3])
        : "r"(a[0]), "r"(a[1]), "r"(a[2]), "r"(a[3]), "r"(b[0]), "r"(b[1]));
}

// ---------------------------------------------------------------------------
// Pass 1: coeffs fp32 -> fp16 (same [j][i*8+m] layout)
// ---------------------------------------------------------------------------
__global__ void __launch_bounds__(256) coef_convert_kernel(const float* __restrict__ c) {
    int idx = blockIdx.x * blockDim.x + threadIdx.x;   // per 4 elements
    float4 v = reinterpret_cast<const float4*>(c)[idx];
    __half2 a = __floats2half2_rn(v.x, v.y);
    __half2 b = __floats2half2_rn(v.z, v.w);
    uint2 o;
    o.x = h2_as_u32(a);
    o.y = h2_as_u32(b);
    reinterpret_cast<uint2*>(g_coefh)[idx] = o;
}

// ---------------------------------------------------------------------------
// Pass 2: warp-specialized FUSED basis + HMMA GEMM
//   out[M,N] = S[M,K] * coefh[N,K]^T
//   S[b][i*8+m] = 0.5*tanh(slope[i][m]*(x[b][i]-center[i][m])) + 0.5
// ---------------------------------------------------------------------------
__global__ void __launch_bounds__(THREADS, 1)
gemm_kernel(const float* __restrict__ x,
            const float* __restrict__ centers,
            const float* __restrict__ slopes,
            float* __restrict__ out) {
    extern __shared__ char smbase[];
    const uint32_t sb32 = smem_u32(smbase);
    const uint32_t sA0 = sb32 + A_OFF;
    const uint32_t sB0 = sb32 + B_OFF;

    const int tid = threadIdx.x;
    const int wid = tid >> 5;
    const int lid = tid & 31;
    const int m0 = blockIdx.y * BM;
    const int n0 = blockIdx.x * BN;

    const bool is_consumer = (wid < 8);

    if (!is_consumer) {
        // =================== PRODUCER PATH (warps 8-11) ====================
        const int ptid = tid - 256;           // 0..127
        const int i_local = ptid & 7;         // k-chunk channel 0..7
        const int rgrp = ptid >> 3;           // 0..15 -> rows rgrp*8 .. +7
        const float* xcol = x + (size_t)(m0 + rgrp * 8) * GIN;
        const __half* Bbase = g_coefh + (size_t)n0 * GK;

        // B loader: 2048 16B chunks per stage, 16 per producer thread
        auto load_B = [&](int kt) {
            uint32_t sbm = sB0 + (kt % BSTAGES) * B_STAGE_BYTES;
            int kofs = kt * BK;
#pragma unroll
            for (int j = 0; j < 16; j++) {
                int c = ptid + j * 128;
                int row = c >> 3;
                int cu = c & 7;
                uint32_t so = (uint32_t)(row * LDS + cu * 8) * 2;
                cp16(sbm + so, Bbase + (size_t)row * GK + kofs + cu * 8);
            }
            asm volatile("cp.async.commit_group;\n" ::: "memory");
        };

        auto fetch_x = [&](int kt, float* xr) {
            int i = kt * 8 + i_local;
#pragma unroll
            for (int r = 0; r < 8; r++)
                xr[r] = xcol[(size_t)r * GIN + i];
        };

        auto produce_A = [&](int kt, const float* xr) {
            int i = kt * 8 + i_local;
            // per-ktile fg load (L2-hot, lanes with same i_local broadcast)
            float4 fa = *reinterpret_cast<const float4*>(slopes + i * 8);
            float4 fb = *reinterpret_cast<const float4*>(slopes + i * 8 + 4);
            float4 ca = *reinterpret_cast<const float4*>(centers + i * 8);
            float4 cb = *reinterpret_cast<const float4*>(centers + i * 8 + 4);
            float f0[8] = {fa.x, fa.y, fa.z, fa.w, fb.x, fb.y, fb.z, fb.w};
            float c0[8] = {ca.x, ca.y, ca.z, ca.w, cb.x, cb.y, cb.z, cb.w};
            float g0[8];
#pragma unroll
            for (int m = 0; m < 8; m++) g0[m] = -f0[m] * c0[m];

            uint4* ap = reinterpret_cast<uint4*>(smbase + A_OFF + (kt & 1) * A_STAGE_BYTES);
#pragma unroll
            for (int r = 0; r < 8; r++) {
                __half h[8];
#pragma unroll
                for (int m = 0; m < 8; m++) {
                    float t = fmaf(f0[m], xr[r], g0[m]);
                    float th;
                    asm("tanh.approx.f32 %0, %1;" : "=f"(th) : "f"(t));
                    h[m] = __float2half_rn(fmaf(0.5f, th, 0.5f));
                }
                uint4 o;
                o.x = h2_as_u32(__halves2half2(h[0], h[1]));
                o.y = h2_as_u32(__halves2half2(h[2], h[3]));
                o.z = h2_as_u32(__halves2half2(h[4], h[5]));
                o.w = h2_as_u32(__halves2half2(h[6], h[7]));
                ap[(rgrp * 8 + r) * 9 + i_local] = o;   // 9 uint4 per 72-half row
            }
        };

        // ---- prologue ----
        {
            float xr0[8];
            fetch_x(0, xr0);
            load_B(0);
            load_B(1);
            produce_A(0, xr0);
            asm volatile("cp.async.wait_group 1;\n" ::: "memory");   // B(0) done
        }
        __syncthreads();   // matches consumer prologue sync

        for (int kt = 0; kt < KT; kt++) {
            float xn[8];
            if (kt + 1 < KT) fetch_x(kt + 1, xn);           // LDGs first
            if (kt + 2 < KT) {
                load_B(kt + 2);                              // independent DMA
            } else {
                asm volatile("cp.async.commit_group;\n" ::: "memory");
            }
            if (kt + 1 < KT) produce_A(kt + 1, xn);          // tanh under MMA shadow
            asm volatile("cp.async.wait_group 1;\n" ::: "memory");  // B(kt+1) done
            __syncthreads();
        }
        return;   // producers exit; consumers store epilogue
    }

    // ===================== CONSUMER PATH (warps 0-7) =======================
    const int wm = wid & 1;        // 64-row slab
    const int wn = wid >> 1;       // 64-col slab

    float d[4][8][4];
#pragma unroll
    for (int mi = 0; mi < 4; mi++)
#pragma unroll
        for (int ni = 0; ni < 8; ni++)
#pragma unroll
            for (int q = 0; q < 4; q++) d[mi][ni][q] = 0.0f;

    // ldmatrix lane addressing (halves)
    const int a_row = wm * 64 + (lid & 15);
    const int a_col = (lid >> 4) * 8;
    const int b_row = wn * 64 + (lid & 7) + (lid >> 4) * 8;
    const int b_col = ((lid >> 3) & 1) * 8;

    __syncthreads();   // A(0), B(0) ready

    for (int kt = 0; kt < KT; kt++) {
        uint32_t sa = sA0 + (kt & 1) * A_STAGE_BYTES;
        uint32_t sbm = sB0 + (kt % BSTAGES) * B_STAGE_BYTES;

#pragma unroll
        for (int ks = 0; ks < 4; ks++) {
            uint32_t a[4][4];
            uint32_t b[8][2];
#pragma unroll
            for (int mi = 0; mi < 4; mi++) {
                uint32_t addr = sa + (uint32_t)((a_row + mi * 16) * LDS + ks * 16 + a_col) * 2;
                ldmatrix_x4(a[mi], addr);
            }
#pragma unroll
            for (int p = 0; p < 4; p++) {
                uint32_t t[4];
                uint32_t addr = sbm + (uint32_t)((b_row + p * 16) * LDS + ks * 16 + b_col) * 2;
                ldmatrix_x4(t, addr);
                b[2 * p][0] = t[0]; b[2 * p][1] = t[1];
                b[2 * p + 1][0] = t[2]; b[2 * p + 1][1] = t[3];
            }
#pragma unroll
            for (int mi = 0; mi < 4; mi++)
#pragma unroll
                for (int ni = 0; ni < 8; ni++)
                    mma_16816(d[mi][ni], a[mi], b[ni]);
        }
        __syncthreads();
    }

    // Epilogue: direct fp32 stores.
    const int er = m0 + wm * 64 + (lid >> 2);
    const int ec = n0 + wn * 64 + (lid & 3) * 2;
#pragma unroll
    for (int mi = 0; mi < 4; mi++) {
#pragma unroll
        for (int ni = 0; ni < 8; ni++) {
            int r = er + mi * 16;
            int c = ec + ni * 8;
            float2 v0 = make_float2(d[mi][ni][0], d[mi][ni][1]);
            float2 v1 = make_float2(d[mi][ni][2], d[mi][ni][3]);
            *reinterpret_cast<float2*>(out + (size_t)r * GN + c) = v0;
            *reinterpret_cast<float2*>(out + (size_t)(r + 8) * GN + c) = v1;
        }
    }
}

// ---------------------------------------------------------------------------
// Launch
// ---------------------------------------------------------------------------
extern "C" void kernel_launch(void* const* d_in, const int* in_sizes, int n_in,
                              void* d_out, int out_size) {
    const float* x       = (const float*)d_in[0];   // (8192, 512)
    const float* coeffs  = (const float*)d_in[1];   // (512, 512, 8)
    const float* centers = (const float*)d_in[2];   // (512, 8)
    const float* slopes  = (const float*)d_in[3];   // (512, 8)
    float* out = (float*)d_out;                     // (8192, 512)

    // Pass 1: coeffs fp32 -> fp16
    coef_convert_kernel<<<(GN * GK / 4) / 256, 256>>>(coeffs);

    // Pass 2: warp-specialized fused basis + HMMA GEMM
    cudaFuncSetAttribute(gemm_kernel, cudaFuncAttributeMaxDynamicSharedMemorySize,
                         SMEM_BYTES);
    dim3 grid(GN / BN, GM / BM);   // (2, 64)
    gemm_kernel<<<grid, THREADS, SMEM_BYTES>>>(x, centers, slopes, out);
}

// round 11
// speedup vs baseline: 1.3117x; 1.0558x over previous
#include <cuda_runtime.h>
#include <cuda_fp16.h>
#include <cstdint>

// ---------------------------------------------------------------------------
// Problem shape (fixed by dataset)
// ---------------------------------------------------------------------------
static constexpr int GM = 8192;          // batch
static constexpr int GN = 512;           // out_count
static constexpr int GIN = 512;          // in_count
static constexpr int NB = 8;             // num_basis
static constexpr int GK = GIN * NB;      // 4096 (reduction dim, (i,m) order)

// GEMM tiling: BM=64, BN=256, BK=64; warp-specialized CTA (192 threads):
//   warps 0-3 : consumers, 1(M) x 4(N), warp tile 64x64, MMA only
//   warps 4-5 : producers, A-tile tanh production + all B cp.async
// 2 CTAs/SM (smem 92KB/CTA), grid 256 -> all 148 SMs busy.
static constexpr int BM = 64, BN = 256, BK = 64;
static constexpr int KT = GK / BK;       // 64 k-tiles
static constexpr int LDS = BK + 8;       // 72 halves row stride (144B, conflict-free)
static constexpr int A_STAGE_BYTES = BM * LDS * 2;   //  9216 (A double-buffered)
static constexpr int B_STAGE_BYTES = BN * LDS * 2;   // 36864 (B double-buffered)

static constexpr int A_OFF = 0;                              // 2 * 9216
static constexpr int B_OFF = 2 * A_STAGE_BYTES;              // 18432
static constexpr int SMEM_BYTES = B_OFF + 2 * B_STAGE_BYTES; // 92160

static constexpr int THREADS = 192;      // 128 consumers + 64 producers

// Scratch (allowed: __device__ globals)
__device__ __half g_coefh[(size_t)GN * GK];   // 4 MB, [j][i*8+m]

// ---------------------------------------------------------------------------
// Helpers
// ---------------------------------------------------------------------------
__device__ __forceinline__ uint32_t h2_as_u32(__half2 v) {
    union { __half2 h; uint32_t u; } cvt;
    cvt.h = v;
    return cvt.u;
}

__device__ __forceinline__ uint32_t smem_u32(const void* p) {
    uint32_t a;
    asm("{ .reg .u64 t; cvta.to.shared.u64 t, %1; cvt.u32.u64 %0, t; }"
        : "=r"(a) : "l"(p));
    return a;
}

__device__ __forceinline__ void cp16(uint32_t dst, const void* src) {
    asm volatile("cp.async.cg.shared.global [%0], [%1], 16;\n" :: "r"(dst), "l"(src));
}

__device__ __forceinline__ void ldmatrix_x4(uint32_t* r, uint32_t addr) {
    asm volatile("ldmatrix.sync.aligned.m8n8.x4.shared.b16 {%0,%1,%2,%3}, [%4];"
                 : "=r"(r[0]), "=r"(r[1]), "=r"(r[2]), "=r"(r[3]) : "r"(addr));
}

__device__ __forceinline__ void mma_16816(float* d, const uint32_t* a, const uint32_t* b) {
    asm volatile(
        "mma.sync.aligned.m16n8k16.row.col.f32.f16.f16.f32 "
        "{%0,%1,%2,%3}, {%4,%5,%6,%7}, {%8,%9}, {%0,%1,%2,%3};"
        : "+f"(d[0]), "+f"(d[1]), "+f"(d[2]), "+f"(d[3])
        : "r"(a[0]), "r"(a[1]), "r"(a[2]), "r"(a[3]), "r"(b[0]), "r"(b[1]));
}

// ---------------------------------------------------------------------------
// Pass 1: coeffs fp32 -> fp16 (same [j][i*8+m] layout)
// ---------------------------------------------------------------------------
__global__ void __launch_bounds__(256) coef_convert_kernel(const float* __restrict__ c) {
    int idx = blockIdx.x * blockDim.x + threadIdx.x;   // per 4 elements
    float4 v = reinterpret_cast<const float4*>(c)[idx];
    __half2 a = __floats2half2_rn(v.x, v.y);
    __half2 b = __floats2half2_rn(v.z, v.w);
    uint2 o;
    o.x = h2_as_u32(a);
    o.y = h2_as_u32(b);
    reinterpret_cast<uint2*>(g_coefh)[idx] = o;
}

// ---------------------------------------------------------------------------
// Pass 2: warp-specialized FUSED basis + HMMA GEMM
//   out[M,N] = S[M,K] * coefh[N,K]^T
//   S[b][i*8+m] = 0.5*tanh(slope[i][m]*(x[b][i]-center[i][m])) + 0.5
// Schedule per iteration kt (producers):
//   load_B(kt+1) -> buffer (kt+1)&1  (freed by consumers at end of kt-1)
//   produce_A(kt+1) -> buffer (kt+1)&1
//   cp.async.wait_group 0 ; __syncthreads
// Consumers: MMA over A(kt),B(kt) ; __syncthreads
// ---------------------------------------------------------------------------
__global__ void __launch_bounds__(THREADS, 2)
gemm_kernel(const float* __restrict__ x,
            const float* __restrict__ centers,
            const float* __restrict__ slopes,
            float* __restrict__ out) {
    extern __shared__ char smbase[];
    const uint32_t sb32 = smem_u32(smbase);
    const uint32_t sA0 = sb32 + A_OFF;
    const uint32_t sB0 = sb32 + B_OFF;

    const int tid = threadIdx.x;
    const int wid = tid >> 5;
    const int lid = tid & 31;
    const int m0 = blockIdx.y * BM;
    const int n0 = blockIdx.x * BN;

    if (wid >= 4) {
        // =================== PRODUCER PATH (warps 4-5, 64 threads) =========
        const int ptid = tid - 128;           // 0..63
        const int i_local = ptid & 7;         // k-chunk channel 0..7
        const int rgrp = ptid >> 3;           // 0..7 -> rows rgrp*8 .. +7
        const float* xcol = x + (size_t)(m0 + rgrp * 8) * GIN;
        const __half* Bbase = g_coefh + (size_t)n0 * GK;

        // B loader: 2048 16B chunks per stage, 32 per producer thread
        auto load_B = [&](int kt) {
            uint32_t sbm = sB0 + (kt & 1) * B_STAGE_BYTES;
            int kofs = kt * BK;
#pragma unroll
            for (int j = 0; j < 32; j++) {
                int c = ptid + j * 64;
                int row = c >> 3;
                int cu = c & 7;
                uint32_t so = (uint32_t)(row * LDS + cu * 8) * 2;
                cp16(sbm + so, Bbase + (size_t)row * GK + kofs + cu * 8);
            }
            asm volatile("cp.async.commit_group;\n" ::: "memory");
        };

        auto fetch_x = [&](int kt, float* xr) {
            int i = kt * 8 + i_local;
#pragma unroll
            for (int r = 0; r < 8; r++)
                xr[r] = xcol[(size_t)r * GIN + i];
        };

        auto produce_A = [&](int kt, const float* xr) {
            int i = kt * 8 + i_local;
            float4 fa = *reinterpret_cast<const float4*>(slopes + i * 8);
            float4 fb = *reinterpret_cast<const float4*>(slopes + i * 8 + 4);
            float4 ca = *reinterpret_cast<const float4*>(centers + i * 8);
            float4 cb = *reinterpret_cast<const float4*>(centers + i * 8 + 4);
            float f0[8] = {fa.x, fa.y, fa.z, fa.w, fb.x, fb.y, fb.z, fb.w};
            float c0[8] = {ca.x, ca.y, ca.z, ca.w, cb.x, cb.y, cb.z, cb.w};
            float g0[8];
#pragma unroll
            for (int m = 0; m < 8; m++) g0[m] = -f0[m] * c0[m];

            uint4* ap = reinterpret_cast<uint4*>(smbase + A_OFF + (kt & 1) * A_STAGE_BYTES);
#pragma unroll
            for (int r = 0; r < 8; r++) {
                __half h[8];
#pragma unroll
                for (int m = 0; m < 8; m++) {
                    float t = fmaf(f0[m], xr[r], g0[m]);
                    float th;
                    asm("tanh.approx.f32 %0, %1;" : "=f"(th) : "f"(t));
                    h[m] = __float2half_rn(fmaf(0.5f, th, 0.5f));
                }
                uint4 o;
                o.x = h2_as_u32(__halves2half2(h[0], h[1]));
                o.y = h2_as_u32(__halves2half2(h[2], h[3]));
                o.z = h2_as_u32(__halves2half2(h[4], h[5]));
                o.w = h2_as_u32(__halves2half2(h[6], h[7]));
                ap[(rgrp * 8 + r) * 9 + i_local] = o;   // 9 uint4 per 72-half row
            }
        };

        // ---- prologue: A(0), B(0) ----
        {
            float xr0[8];
            fetch_x(0, xr0);
            load_B(0);
            produce_A(0, xr0);
            asm volatile("cp.async.wait_group 0;\n" ::: "memory");
        }
        __syncthreads();

        for (int kt = 0; kt < KT; kt++) {
            if (kt + 1 < KT) {
                float xn[8];
                fetch_x(kt + 1, xn);            // LDGs first (latency)
                load_B(kt + 1);                 // DMA into freed buffer
                produce_A(kt + 1, xn);          // tanh under consumer MMA shadow
                asm volatile("cp.async.wait_group 0;\n" ::: "memory");
            }
            __syncthreads();
        }
        return;
    }

    // ===================== CONSUMER PATH (warps 0-3) =======================
    const int wn = wid;            // 64-col slab

    float d[4][8][4];
#pragma unroll
    for (int mi = 0; mi < 4; mi++)
#pragma unroll
        for (int ni = 0; ni < 8; ni++)
#pragma unroll
            for (int q = 0; q < 4; q++) d[mi][ni][q] = 0.0f;

    // ldmatrix lane addressing (halves)
    const int a_row = (lid & 15);
    const int a_col = (lid >> 4) * 8;
    const int b_row = wn * 64 + (lid & 7) + (lid >> 4) * 8;
    const int b_col = ((lid >> 3) & 1) * 8;

    __syncthreads();   // A(0), B(0) ready

    for (int kt = 0; kt < KT; kt++) {
        uint32_t sa = sA0 + (kt & 1) * A_STAGE_BYTES;
        uint32_t sbm = sB0 + (kt & 1) * B_STAGE_BYTES;

#pragma unroll
        for (int ks = 0; ks < 4; ks++) {
            uint32_t a[4][4];
            uint32_t b[8][2];
#pragma unroll
            for (int mi = 0; mi < 4; mi++) {
                uint32_t addr = sa + (uint32_t)((a_row + mi * 16) * LDS + ks * 16 + a_col) * 2;
                ldmatrix_x4(a[mi], addr);
            }
#pragma unroll
            for (int p = 0; p < 4; p++) {
                uint32_t t[4];
                uint32_t addr = sbm + (uint32_t)((b_row + p * 16) * LDS + ks * 16 + b_col) * 2;
                ldmatrix_x4(t, addr);
                b[2 * p][0] = t[0]; b[2 * p][1] = t[1];
                b[2 * p + 1][0] = t[2]; b[2 * p + 1][1] = t[3];
            }
#pragma unroll
            for (int mi = 0; mi < 4; mi++)
#pragma unroll
                for (int ni = 0; ni < 8; ni++)
                    mma_16816(d[mi][ni], a[mi], b[ni]);
        }
        __syncthreads();
    }

    // Epilogue: direct fp32 stores.
    const int er = m0 + (lid >> 2);
    const int ec = n0 + wn * 64 + (lid & 3) * 2;
#pragma unroll
    for (int mi = 0; mi < 4; mi++) {
#pragma unroll
        for (int ni = 0; ni < 8; ni++) {
            int r = er + mi * 16;
            int c = ec + ni * 8;
            float2 v0 = make_float2(d[mi][ni][0], d[mi][ni][1]);
            float2 v1 = make_float2(d[mi][ni][2], d[mi][ni][3]);
            *reinterpret_cast<float2*>(out + (size_t)r * GN + c) = v0;
            *reinterpret_cast<float2*>(out + (size_t)(r + 8) * GN + c) = v1;
        }
    }
}

// ---------------------------------------------------------------------------
// Launch
// ---------------------------------------------------------------------------
extern "C" void kernel_launch(void* const* d_in, const int* in_sizes, int n_in,
                              void* d_out, int out_size) {
    const float* x       = (const float*)d_in[0];   // (8192, 512)
    const float* coeffs  = (const float*)d_in[1];   // (512, 512, 8)
    const float* centers = (const float*)d_in[2];   // (512, 8)
    const float* slopes  = (const float*)d_in[3];   // (512, 8)
    float* out = (float*)d_out;                     // (8192, 512)

    // Pass 1: coeffs fp32 -> fp16
    coef_convert_kernel<<<(GN * GK / 4) / 256, 256>>>(coeffs);

    // Pass 2: warp-specialized fused basis + HMMA GEMM, 2 CTAs/SM
    cudaFuncSetAttribute(gemm_kernel, cudaFuncAttributeMaxDynamicSharedMemorySize,
                         SMEM_BYTES);
    dim3 grid(GN / BN, GM / BM);   // (2, 128) = 256 CTAs
    gemm_kernel<<<grid, THREADS, SMEM_BYTES>>>(x, centers, slopes, out);
}